// round 16
// baseline (speedup 1.0000x reference)
#include <cuda_runtime.h>
#include <cstdint>

#define BATCH   32
#define NPRED   8400
#define NCLS    80
#define ROWF    85
#define KPRE    512
#define MAXOUT  100
#define RPB     120         // rows per k_score block: 120*85*4 = 40800 B smem
#define CONF_TH 0.25f
#define IOU_TH  0.45f
#define CLS_OFF 4096.0f
#define FULLM   0xFFFFFFFFu

// Scratch (no allocations allowed -> device globals)
__device__ unsigned long long g_keys[BATCH * NPRED];
__device__ unsigned long long g_topk[BATCH * KPRE];
__device__ float              g_box[5 * BATCH * KPRE];   // SoA: x1,y1,x2,y2,area (class-offset applied)
__device__ float              g_det[BATCH * KPRE * 7];   // x1,y1,x2,y2,obj,conf,cls
__device__ unsigned char      g_validb[BATCH * KPRE];
__device__ unsigned int       g_sup[BATCH * KPRE * 16];  // 1 MB suppression bitmask (upper-tri valid)

// ---------------------------------------------------------------------------
// K1: streaming score pass. Block stages 120 rows into smem with coalesced
// LDG.128, then thread-per-row PURE MAX via 4 independent FMNMX chains
// (argmax deferred to k_gather, which touches only 512 rows per batch).
// key = (score_bits<<32) | ~n  (unique).
// ---------------------------------------------------------------------------
__global__ void __launch_bounds__(128) k_score(const float* __restrict__ pred) {
    __shared__ float srow[RPB * ROWF];     // 40800 B
    int tid = threadIdx.x;                 // 128
    int b = blockIdx.y;
    int row0 = blockIdx.x * RPB;

    // base element index multiple of 4: RPB*ROWF = 10200, NPRED*ROWF = 714000
    const float4* src = (const float4*)(pred + ((size_t)b * NPRED + row0) * ROWF);
    float4* dst4 = (float4*)srow;
#pragma unroll
    for (int i = 0; i < RPB * ROWF / 4 / 128 + 1; i++) {
        int idx = i * 128 + tid;
        if (idx < RPB * ROWF / 4) dst4[idx] = src[idx];
    }
    __syncthreads();

    if (tid < RPB) {
        const float* row = srow + tid * ROWF;   // stride 85 words: conflict-free
        // 4 independent running-max chains over the 80 class scores
        float m0 = row[5], m1 = row[6], m2 = row[7], m3 = row[8];
#pragma unroll
        for (int c = 9; c < 5 + NCLS; c += 4) {
            m0 = fmaxf(m0, row[c]);
            m1 = fmaxf(m1, row[c + 1]);
            m2 = fmaxf(m2, row[c + 2]);
            m3 = fmaxf(m3, row[c + 3]);
        }
        float bv = fmaxf(fmaxf(m0, m1), fmaxf(m2, m3));
        float score = row[4] * bv;                // >= 0
        unsigned sb = __float_as_uint(score);     // positive-float bit order == int order
        int n = row0 + tid;
        g_keys[(size_t)b * NPRED + n] =
            ((unsigned long long)sb << 32) | (unsigned)(~(unsigned)n);
    }
}

// ---------------------------------------------------------------------------
// K2: per-batch conf (= min(0.25, max score)) + exact top-512 radix-select on
// unique 64-bit keys + bitonic sort descending. One 512-thread block / batch.
// Early-exit: when the chosen bucket holds exactly `rem` keys, the pivot is
// the MIN of all keys matching the prefix (counting argument: all of them are
// in the top-KPRE) -> one scan + 64-bit atomicMin replaces remaining passes.
// ---------------------------------------------------------------------------
__global__ void k_select() {
    extern __shared__ unsigned long long s_keys[];   // NPRED + KPRE entries
    unsigned long long* topsm = s_keys + NPRED;

    __shared__ unsigned int        hist[256];
    __shared__ unsigned int        wmax[16];
    __shared__ unsigned int        sh_confb;
    __shared__ unsigned long long  sh_prefix;
    __shared__ unsigned long long  sh_pivot;
    __shared__ int                 sh_remaining;
    __shared__ int                 sh_done;
    __shared__ unsigned int        cnt;

    int b = blockIdx.x;
    int tid = threadIdx.x;                 // 512
    int warp = tid >> 5, lane = tid & 31;  // 16 warps
    const int NITER = (NPRED + 511) / 512; // uniform trip count (17)

    // load keys + running max of score field
    unsigned mymax = 0u;
    for (int i = tid; i < NPRED; i += 512) {
        unsigned long long k = g_keys[(size_t)b * NPRED + i];
        s_keys[i] = k;
        unsigned sb = (unsigned)(k >> 32);
        mymax = mymax > sb ? mymax : sb;
    }
#pragma unroll
    for (int off = 16; off; off >>= 1) {
        unsigned v = __shfl_xor_sync(FULLM, mymax, off);
        mymax = mymax > v ? mymax : v;
    }
    if (lane == 0) wmax[warp] = mymax;
    __syncthreads();
    if (tid < 32) {
        unsigned v = (lane < 16) ? wmax[lane] : 0u;
#pragma unroll
        for (int off = 16; off; off >>= 1) {
            unsigned o = __shfl_xor_sync(FULLM, v, off);
            v = v > o ? v : o;
        }
        if (lane == 0) {
            float conf = fminf(CONF_TH, __uint_as_float(v));
            sh_confb = __float_as_uint(conf);
            sh_prefix = 0ull;
            sh_pivot = ~0ull;
            sh_remaining = KPRE;
            sh_done = 0;
        }
    }
    __syncthreads();
    unsigned confb = sh_confb;

    // radix select with early exit. Pass p=7 also applies the conf mask
    // on the fly (score<conf -> score field 0) and writes it back.
    int done_p = -1;
    for (int p = 7; p >= 0; p--) {
        if (tid < 256) hist[tid] = 0u;
        __syncthreads();
        unsigned long long pref = sh_prefix;
        // uniform trip count: every lane executes __match_any every iteration
        for (int it = 0; it < NITER; it++) {
            int i = it * 512 + tid;
            unsigned bucket = 0x100u;      // sentinel: inactive / non-matching
            if (i < NPRED) {
                unsigned long long k = s_keys[i];
                if (p == 7) {
                    // fold conf-mask sweep into the first pass
                    if ((unsigned)(k >> 32) < confb) {
                        k &= 0xFFFFFFFFull;
                        s_keys[i] = k;
                    }
                    bucket = (unsigned)(k >> 56);
                } else if ((k >> ((p + 1) * 8)) == pref) {
                    bucket = (unsigned)(k >> (p * 8)) & 0xFFu;
                }
            }
            unsigned peers = __match_any_sync(FULLM, bucket);
            if (bucket != 0x100u && ((__ffs(peers) - 1) == lane))
                atomicAdd(&hist[bucket], __popc(peers));
        }
        __syncthreads();
        if (tid < 32) {
            int rem = sh_remaining;
            unsigned s = 0;
#pragma unroll
            for (int q = 0; q < 8; q++) s += hist[(lane << 3) + q];
            unsigned S = s;                // inclusive suffix sum across lanes
#pragma unroll
            for (int off = 1; off < 32; off <<= 1) {
                unsigned v = __shfl_down_sync(FULLM, S, off);
                if (lane + off < 32) S += v;
            }
            unsigned bal = __ballot_sync(FULLM, (int)S >= rem);
            int L = 31 - __clz(bal);       // highest lane group reaching rem
            if (lane == L) {
                int cum = (int)(S - s);    // suffix excluding this group
                for (int bb = (L << 3) + 7; bb >= (L << 3); bb--) {
                    cum += (int)hist[bb];
                    if (cum >= rem) {
                        int newrem = rem - (cum - (int)hist[bb]);
                        sh_remaining = newrem;
                        sh_prefix = (pref << 8) | (unsigned)bb;
                        if ((int)hist[bb] == newrem) sh_done = 1;
                        break;
                    }
                }
            }
        }
        __syncthreads();
        if (sh_done) { done_p = p; break; }   // uniform (smem after barrier)
    }

    if (done_p >= 0) {
        // pivot = min over keys matching sh_prefix (all are in top-KPRE)
        unsigned long long pref = sh_prefix;
        int shift = done_p * 8;
        for (int i = tid; i < NPRED; i += 512) {
            unsigned long long k = s_keys[i];
            if ((k >> shift) == pref)
                atomicMin(&sh_pivot, k);
        }
        __syncthreads();
    } else {
        if (tid == 0) sh_pivot = sh_prefix;   // full 8-pass path: prefix IS the key
        __syncthreads();
    }

    unsigned long long pivot = sh_pivot;   // exact 512th-largest key
    if (tid == 0) cnt = 0u;
    __syncthreads();

    // compact: keys unique -> exactly KPRE keys >= pivot
    for (int i = tid; i < NPRED; i += 512) {
        unsigned long long k = s_keys[i];
        if (k >= pivot) {
            unsigned pos = atomicAdd(&cnt, 1u);
            topsm[pos] = k;
        }
    }
    __syncthreads();

    // bitonic sort descending (512 elems, 512 threads)
    for (int kk = 2; kk <= KPRE; kk <<= 1) {
        for (int j = kk >> 1; j > 0; j >>= 1) {
            int ixj = tid ^ j;
            if (ixj > tid) {
                bool up = ((tid & kk) == 0);
                unsigned long long a = topsm[tid], c = topsm[ixj];
                bool sw = up ? (a < c) : (a > c);
                if (sw) { topsm[tid] = c; topsm[ixj] = a; }
            }
            __syncthreads();
        }
    }

    for (int i = tid; i < KPRE; i += 512)
        g_topk[(size_t)b * KPRE + i] = topsm[i];
}

// ---------------------------------------------------------------------------
// K3: gather selected rows -> boxes (class-offset) + dets + valid bytes.
// Grid (64, BATCH) x 256 threads, one warp per entry: latency fully hidden.
// Argmax over 80 classes done here (only 512 rows per batch).
// ---------------------------------------------------------------------------
__global__ void k_gather(const float* __restrict__ pred) {
    int warp = threadIdx.x >> 5, lane = threadIdx.x & 31;
    int b = blockIdx.y;
    int e = blockIdx.x * 8 + warp;

    unsigned long long key = g_topk[(size_t)b * KPRE + e];
    unsigned sb = (unsigned)(key >> 32);
    int n = (int)(~(unsigned)key);
    const float* row = pred + ((size_t)b * NPRED + n) * ROWF;

    float bv = -1.f; int bi = 0;
#pragma unroll
    for (int i = 0; i < 3; i++) {
        int c = lane + i * 32;
        if (c < NCLS) {
            float v = row[5 + c];
            if (v > bv) { bv = v; bi = c; }
        }
    }
#pragma unroll
    for (int off = 16; off; off >>= 1) {
        float ov = __shfl_xor_sync(FULLM, bv, off);
        int   oi = __shfl_xor_sync(FULLM, bi, off);
        if (ov > bv || (ov == bv && oi < bi)) { bv = ov; bi = oi; }
    }
    if (lane == 0) {
        float cx = row[0], cy = row[1], w = row[2], h = row[3], obj = row[4];
        float x1 = cx - 0.5f * w, y1 = cy - 0.5f * h;
        float x2 = cx + 0.5f * w, y2 = cy + 0.5f * h;
        float off = (float)bi * CLS_OFF;
        int base = b * KPRE + e;
        g_box[0 * BATCH * KPRE + base] = x1 + off;
        g_box[1 * BATCH * KPRE + base] = y1 + off;
        g_box[2 * BATCH * KPRE + base] = x2 + off;
        g_box[3 * BATCH * KPRE + base] = y2 + off;
        g_box[4 * BATCH * KPRE + base] = (x2 - x1) * (y2 - y1);
        float* d = g_det + (size_t)base * 7;
        d[0] = x1; d[1] = y1; d[2] = x2; d[3] = y2;
        d[4] = obj; d[5] = bv; d[6] = (float)bi;
        g_validb[base] = (sb != 0u) ? 1 : 0;   // unconditional -> no init kernel
    }
}

// ---------------------------------------------------------------------------
// K4: suppression bitmask, UPPER TRIANGLE ONLY: row i gets words wd >= i>>5.
// (Greedy NMS processes kept boxes in increasing index; when i is kept, all
// alive bits j<i are already 0, so lower-triangle words are never consumed.)
// Grid (32, BATCH) x 512 threads: one warp per row i, ballot forms each word.
// ---------------------------------------------------------------------------
__global__ void k_iou() {
    __shared__ float sx1[KPRE], sy1[KPRE], sx2[KPRE], sy2[KPRE], sar[KPRE];
    int b = blockIdx.y;
    int tid = threadIdx.x;                 // 512
    int warp = tid >> 5, lane = tid & 31;  // 16 warps

    {
        int base = b * KPRE + tid;
        sx1[tid] = g_box[0 * BATCH * KPRE + base];
        sy1[tid] = g_box[1 * BATCH * KPRE + base];
        sx2[tid] = g_box[2 * BATCH * KPRE + base];
        sy2[tid] = g_box[3 * BATCH * KPRE + base];
        sar[tid] = g_box[4 * BATCH * KPRE + base];
    }
    __syncthreads();

    int i = blockIdx.x * 16 + warp;        // this warp's row
    float ax1 = sx1[i], ay1 = sy1[i], ax2 = sx2[i], ay2 = sy2[i], aa = sar[i];
    unsigned* dst = g_sup + ((size_t)b * KPRE + i) * 16;

    for (int wd = (i >> 5); wd < 16; wd++) {
        int j = (wd << 5) + lane;
        float ix1 = fmaxf(ax1, sx1[j]);
        float iy1 = fmaxf(ay1, sy1[j]);
        float ix2 = fminf(ax2, sx2[j]);
        float iy2 = fminf(ay2, sy2[j]);
        float iw = fmaxf(ix2 - ix1, 0.f);
        float ih = fmaxf(iy2 - iy1, 0.f);
        float inter = iw * ih;
        float uni = aa + sar[j] - inter;
        float iou = inter / (uni + 1e-9f);
        unsigned bits = __ballot_sync(FULLM, iou > IOU_TH);
        if (lane == 0) dst[wd] = bits;
    }
}

// ---------------------------------------------------------------------------
// K5: kept-box-centric greedy NMS (single warp, register-resident alive mask,
// early exit at 100 kept) + emit. One block (256 threads) per batch.
// ---------------------------------------------------------------------------
__global__ void k_nms(float* __restrict__ out, int out_size) {
    __shared__ unsigned ssup[KPRE * 16];   // 32 KB
    __shared__ unsigned svalid[16];
    __shared__ int skept[MAXOUT];
    __shared__ int snk;

    int b = blockIdx.x, tid = threadIdx.x;   // 256

    // stage suppression mask (L2-resident) into smem, vectorized
    {
        const uint4* src = (const uint4*)(g_sup + (size_t)b * KPRE * 16);
        uint4* dstv = (uint4*)ssup;
        for (int i = tid; i < KPRE * 16 / 4; i += 256) dstv[i] = src[i];
    }
    // build valid bitmask from bytes (uniform full-warp ballots)
#pragma unroll
    for (int r = 0; r < 2; r++) {
        int idx = r * 256 + tid;
        bool v = g_validb[b * KPRE + idx] != 0;
        unsigned w = __ballot_sync(FULLM, v);
        if ((tid & 31) == 0) svalid[idx >> 5] = w;
    }
    __syncthreads();

    if (tid < 32) {
        int lane = tid;
        unsigned alive = (lane < 16) ? svalid[lane] : 0u;
        int nk = 0;
        while (nk < MAXOUT) {
            unsigned bal = __ballot_sync(FULLM, alive != 0u);
            if (!bal) break;
            int tl = __ffs(bal) - 1;                       // first lane with alive bits
            unsigned w = __shfl_sync(FULLM, alive, tl);
            int bit = __ffs(w) - 1;
            int i = (tl << 5) + bit;                       // first alive index = next kept
            if (lane == 0) skept[nk] = i;
            nk++;
            unsigned sup = (lane < 16) ? ssup[i * 16 + lane] : 0u;
            alive &= ~sup;                                 // suppress overlapping later boxes
            if (lane == tl) alive &= ~(1u << bit);         // self
        }
        if (lane == 0) snk = nk;
    }
    __syncthreads();

    int nk = snk;
    float* dets = out + (size_t)b * MAXOUT * 7;
    bool has_mask = (out_size >= BATCH * MAXOUT * 7 + BATCH * MAXOUT);
    float* mask = out + (size_t)BATCH * MAXOUT * 7 + (size_t)b * MAXOUT;

    if (tid < MAXOUT) {
        int r = tid;
        if (r < nk) {
            int i = skept[r];
            const float* d = g_det + ((size_t)b * KPRE + i) * 7;
            float* o = dets + (size_t)r * 7;
#pragma unroll
            for (int c = 0; c < 7; c++) o[c] = d[c];
            if (has_mask) mask[r] = 1.0f;
        } else {
            float* o = dets + (size_t)r * 7;
#pragma unroll
            for (int c = 0; c < 7; c++) o[c] = 0.f;
            if (has_mask) mask[r] = 0.f;
        }
    }
}

// ---------------------------------------------------------------------------
extern "C" void kernel_launch(void* const* d_in, const int* in_sizes, int n_in,
                              void* d_out, int out_size) {
    (void)in_sizes; (void)n_in;
    const float* pred = (const float*)d_in[0];
    float* out = (float*)d_out;

    static_assert(NPRED % RPB == 0, "rows per block");
    static_assert((RPB * ROWF) % 4 == 0, "float4 staging");
    static_assert((NPRED * ROWF) % 4 == 0, "float4 batch base");
    static_assert((NCLS - 4) % 4 == 0, "4-way max chains cover classes");

    cudaFuncSetAttribute(k_select, cudaFuncAttributeMaxDynamicSharedMemorySize,
                         (NPRED + KPRE) * 8);

    dim3 gs(NPRED / RPB, BATCH);           // (70, 32)
    k_score<<<gs, 128>>>(pred);
    k_select<<<BATCH, 512, (NPRED + KPRE) * 8>>>();
    dim3 gg(KPRE / 8, BATCH);              // (64, 32)
    k_gather<<<gg, 256>>>(pred);
    dim3 gi(KPRE / 16, BATCH);             // (32, 32)
    k_iou<<<gi, 512>>>();
    k_nms<<<BATCH, 256>>>(out, out_size);
}

// round 17
// speedup vs baseline: 1.5181x; 1.5181x over previous
#include <cuda_runtime.h>
#include <cstdint>

#define BATCH   32
#define NPRED   8400
#define NCLS    80
#define ROWF    85
#define KPRE    512
#define MAXOUT  100
#define RPB     120         // rows per k_score block: 120*85*4 = 40800 B smem
#define CONF_TH 0.25f
#define IOU_TH  0.45f
#define CLS_OFF 4096.0f
#define FULLM   0xFFFFFFFFu

// Scratch (no allocations allowed -> device globals)
__device__ unsigned long long g_keys[BATCH * NPRED];
__device__ unsigned long long g_topk[BATCH * KPRE];
__device__ float              g_box[5 * BATCH * KPRE];   // SoA: x1,y1,x2,y2,area (class-offset applied)
__device__ float              g_det[BATCH * KPRE * 7];   // x1,y1,x2,y2,obj,conf,cls
__device__ unsigned char      g_validb[BATCH * KPRE];
__device__ unsigned int       g_sup[BATCH * KPRE * 16];  // 1 MB suppression bitmask (upper-tri valid)

// ---------------------------------------------------------------------------
// K1: streaming score pass. Block stages 120 rows into smem with coalesced
// LDG.128, then thread-per-row PURE MAX via 4 independent FMNMX chains
// (argmax deferred to k_gather, which touches only 512 rows per batch).
// key = (score_bits<<32) | ~n  (unique).
// ---------------------------------------------------------------------------
__global__ void __launch_bounds__(128) k_score(const float* __restrict__ pred) {
    __shared__ float srow[RPB * ROWF];     // 40800 B
    int tid = threadIdx.x;                 // 128
    int b = blockIdx.y;
    int row0 = blockIdx.x * RPB;

    // base element index multiple of 4: RPB*ROWF = 10200, NPRED*ROWF = 714000
    const float4* src = (const float4*)(pred + ((size_t)b * NPRED + row0) * ROWF);
    float4* dst4 = (float4*)srow;
#pragma unroll
    for (int i = 0; i < RPB * ROWF / 4 / 128 + 1; i++) {
        int idx = i * 128 + tid;
        if (idx < RPB * ROWF / 4) dst4[idx] = src[idx];
    }
    __syncthreads();

    if (tid < RPB) {
        const float* row = srow + tid * ROWF;   // stride 85 words: conflict-free
        // 4 independent running-max chains over the 80 class scores
        float m0 = row[5], m1 = row[6], m2 = row[7], m3 = row[8];
#pragma unroll
        for (int c = 9; c < 5 + NCLS; c += 4) {
            m0 = fmaxf(m0, row[c]);
            m1 = fmaxf(m1, row[c + 1]);
            m2 = fmaxf(m2, row[c + 2]);
            m3 = fmaxf(m3, row[c + 3]);
        }
        float bv = fmaxf(fmaxf(m0, m1), fmaxf(m2, m3));
        float score = row[4] * bv;                // >= 0
        unsigned sb = __float_as_uint(score);     // positive-float bit order == int order
        int n = row0 + tid;
        g_keys[(size_t)b * NPRED + n] =
            ((unsigned long long)sb << 32) | (unsigned)(~(unsigned)n);
    }
}

// ---------------------------------------------------------------------------
// K2: per-batch conf (= min(0.25, max score)) + exact top-512 radix-select on
// unique 64-bit keys + bitonic sort descending. One 512-thread block / batch.
// EXACT early-exit: after a pass, m = hist[chosen] keys share the new prefix;
// when m <= 256, collect them and pick the rem-th largest by rank counting
// (rem <= m by construction; keys unique) -> same pivot the remaining passes
// would produce, without scanning 8400 keys per remaining pass.
// ---------------------------------------------------------------------------
__global__ void k_select() {
    extern __shared__ unsigned long long s_keys[];   // NPRED + KPRE entries
    unsigned long long* topsm = s_keys + NPRED;

    __shared__ unsigned int        hist[256];
    __shared__ unsigned int        wmax[16];
    __shared__ unsigned int        sh_confb;
    __shared__ unsigned long long  sh_prefix;
    __shared__ unsigned long long  sh_pivot;
    __shared__ int                 sh_remaining;
    __shared__ int                 sh_m;
    __shared__ int                 sh_done;
    __shared__ unsigned int        cnt;
    __shared__ unsigned long long  cand[256];
    __shared__ unsigned int        ccnt;

    int b = blockIdx.x;
    int tid = threadIdx.x;                 // 512
    int warp = tid >> 5, lane = tid & 31;  // 16 warps
    const int NITER = (NPRED + 511) / 512; // uniform trip count (17)

    // load keys + running max of score field
    unsigned mymax = 0u;
    for (int i = tid; i < NPRED; i += 512) {
        unsigned long long k = g_keys[(size_t)b * NPRED + i];
        s_keys[i] = k;
        unsigned sb = (unsigned)(k >> 32);
        mymax = mymax > sb ? mymax : sb;
    }
#pragma unroll
    for (int off = 16; off; off >>= 1) {
        unsigned v = __shfl_xor_sync(FULLM, mymax, off);
        mymax = mymax > v ? mymax : v;
    }
    if (lane == 0) wmax[warp] = mymax;
    __syncthreads();
    if (tid < 32) {
        unsigned v = (lane < 16) ? wmax[lane] : 0u;
#pragma unroll
        for (int off = 16; off; off >>= 1) {
            unsigned o = __shfl_xor_sync(FULLM, v, off);
            v = v > o ? v : o;
        }
        if (lane == 0) {
            float conf = fminf(CONF_TH, __uint_as_float(v));
            sh_confb = __float_as_uint(conf);
            sh_prefix = 0ull;
            sh_remaining = KPRE;
            sh_done = 0;
        }
    }
    __syncthreads();
    unsigned confb = sh_confb;

    // mask invalid (score < conf) -> score field 0 (acts as -inf; index kept)
    for (int i = tid; i < NPRED; i += 512) {
        unsigned long long k = s_keys[i];
        if ((unsigned)(k >> 32) < confb) s_keys[i] = k & 0xFFFFFFFFull;
    }
    __syncthreads();

    // radix select: find exact KPRE-th largest key (early-exit when few
    // candidates remain; full 8-pass fallback otherwise)
    for (int p = 7; p >= 0; p--) {
        if (tid < 256) hist[tid] = 0u;
        __syncthreads();
        unsigned long long pref = sh_prefix;
        // uniform trip count: every lane executes __match_any every iteration
        for (int it = 0; it < NITER; it++) {
            int i = it * 512 + tid;
            unsigned bucket = 0x100u;      // sentinel: inactive / non-matching
            if (i < NPRED) {
                unsigned long long k = s_keys[i];
                bool match = (p == 7) || ((k >> ((p + 1) * 8)) == pref);
                if (match) bucket = (unsigned)(k >> (p * 8)) & 0xFFu;
            }
            unsigned peers = __match_any_sync(FULLM, bucket);
            if (bucket != 0x100u && ((__ffs(peers) - 1) == lane))
                atomicAdd(&hist[bucket], __popc(peers));
        }
        __syncthreads();
        if (tid < 32) {
            int rem = sh_remaining;
            unsigned s = 0;
#pragma unroll
            for (int q = 0; q < 8; q++) s += hist[(lane << 3) + q];
            unsigned S = s;                // inclusive suffix sum across lanes
#pragma unroll
            for (int off = 1; off < 32; off <<= 1) {
                unsigned v = __shfl_down_sync(FULLM, S, off);
                if (lane + off < 32) S += v;
            }
            unsigned bal = __ballot_sync(FULLM, (int)S >= rem);
            int L = 31 - __clz(bal);       // highest lane group reaching rem
            if (lane == L) {
                int cum = (int)(S - s);    // suffix excluding this group
                for (int bb = (L << 3) + 7; bb >= (L << 3); bb--) {
                    cum += (int)hist[bb];
                    if (cum >= rem) {
                        sh_remaining = rem - (cum - (int)hist[bb]);
                        sh_prefix = (pref << 8) | (unsigned)bb;
                        sh_m = (int)hist[bb];
                        break;
                    }
                }
            }
        }
        __syncthreads();
        if (p > 0 && sh_m <= 256) {
            // EXACT early exit: collect the m keys matching the prefix and
            // pick the rem-th largest by rank (1 <= rem <= m guaranteed).
            if (tid == 0) ccnt = 0u;
            __syncthreads();
            unsigned long long pfx = sh_prefix;
            int shift = p * 8;
            for (int i = tid; i < NPRED; i += 512) {
                unsigned long long k = s_keys[i];
                if ((k >> shift) == pfx) {
                    unsigned pos = atomicAdd(&ccnt, 1u);
                    cand[pos] = k;
                }
            }
            __syncthreads();
            int m = (int)ccnt;
            int rem = sh_remaining;
            if (tid < m) {
                unsigned long long k = cand[tid];
                int g = 0;
                for (int j = 0; j < m; j++) g += (cand[j] > k);
                if (g == rem - 1) sh_pivot = k;   // unique keys -> exactly one
            }
            if (tid == 0) sh_done = 1;
            __syncthreads();
            break;                          // uniform (smem after barrier)
        }
    }
    if (!sh_done) {                         // full 8-pass path: prefix IS the key
        if (tid == 0) sh_pivot = sh_prefix;
        __syncthreads();
    }

    unsigned long long pivot = sh_pivot;    // exact 512th-largest key
    if (tid == 0) cnt = 0u;
    __syncthreads();

    // compact: keys unique -> exactly KPRE keys >= pivot
    for (int i = tid; i < NPRED; i += 512) {
        unsigned long long k = s_keys[i];
        if (k >= pivot) {
            unsigned pos = atomicAdd(&cnt, 1u);
            topsm[pos] = k;
        }
    }
    __syncthreads();

    // bitonic sort descending (512 elems, 512 threads)
    for (int kk = 2; kk <= KPRE; kk <<= 1) {
        for (int j = kk >> 1; j > 0; j >>= 1) {
            int ixj = tid ^ j;
            if (ixj > tid) {
                bool up = ((tid & kk) == 0);
                unsigned long long a = topsm[tid], c = topsm[ixj];
                bool sw = up ? (a < c) : (a > c);
                if (sw) { topsm[tid] = c; topsm[ixj] = a; }
            }
            __syncthreads();
        }
    }

    for (int i = tid; i < KPRE; i += 512)
        g_topk[(size_t)b * KPRE + i] = topsm[i];
}

// ---------------------------------------------------------------------------
// K3: gather selected rows -> boxes (class-offset) + dets + valid bytes.
// Grid (64, BATCH) x 256 threads, one warp per entry: latency fully hidden.
// Argmax over 80 classes done here (only 512 rows per batch).
// ---------------------------------------------------------------------------
__global__ void k_gather(const float* __restrict__ pred) {
    int warp = threadIdx.x >> 5, lane = threadIdx.x & 31;
    int b = blockIdx.y;
    int e = blockIdx.x * 8 + warp;

    unsigned long long key = g_topk[(size_t)b * KPRE + e];
    unsigned sb = (unsigned)(key >> 32);
    int n = (int)(~(unsigned)key);
    const float* row = pred + ((size_t)b * NPRED + n) * ROWF;

    float bv = -1.f; int bi = 0;
#pragma unroll
    for (int i = 0; i < 3; i++) {
        int c = lane + i * 32;
        if (c < NCLS) {
            float v = row[5 + c];
            if (v > bv) { bv = v; bi = c; }
        }
    }
#pragma unroll
    for (int off = 16; off; off >>= 1) {
        float ov = __shfl_xor_sync(FULLM, bv, off);
        int   oi = __shfl_xor_sync(FULLM, bi, off);
        if (ov > bv || (ov == bv && oi < bi)) { bv = ov; bi = oi; }
    }
    if (lane == 0) {
        float cx = row[0], cy = row[1], w = row[2], h = row[3], obj = row[4];
        float x1 = cx - 0.5f * w, y1 = cy - 0.5f * h;
        float x2 = cx + 0.5f * w, y2 = cy + 0.5f * h;
        float off = (float)bi * CLS_OFF;
        int base = b * KPRE + e;
        g_box[0 * BATCH * KPRE + base] = x1 + off;
        g_box[1 * BATCH * KPRE + base] = y1 + off;
        g_box[2 * BATCH * KPRE + base] = x2 + off;
        g_box[3 * BATCH * KPRE + base] = y2 + off;
        g_box[4 * BATCH * KPRE + base] = (x2 - x1) * (y2 - y1);
        float* d = g_det + (size_t)base * 7;
        d[0] = x1; d[1] = y1; d[2] = x2; d[3] = y2;
        d[4] = obj; d[5] = bv; d[6] = (float)bi;
        g_validb[base] = (sb != 0u) ? 1 : 0;   // unconditional -> no init kernel
    }
}

// ---------------------------------------------------------------------------
// K4: suppression bitmask, UPPER TRIANGLE ONLY: row i gets words wd >= i>>5.
// (Greedy NMS processes kept boxes in increasing index; when i is kept, all
// alive bits j<i are already 0, so lower-triangle words are never consumed.)
// Grid (32, BATCH) x 512 threads: one warp per row i, ballot forms each word.
// ---------------------------------------------------------------------------
__global__ void k_iou() {
    __shared__ float sx1[KPRE], sy1[KPRE], sx2[KPRE], sy2[KPRE], sar[KPRE];
    int b = blockIdx.y;
    int tid = threadIdx.x;                 // 512
    int warp = tid >> 5, lane = tid & 31;  // 16 warps

    {
        int base = b * KPRE + tid;
        sx1[tid] = g_box[0 * BATCH * KPRE + base];
        sy1[tid] = g_box[1 * BATCH * KPRE + base];
        sx2[tid] = g_box[2 * BATCH * KPRE + base];
        sy2[tid] = g_box[3 * BATCH * KPRE + base];
        sar[tid] = g_box[4 * BATCH * KPRE + base];
    }
    __syncthreads();

    int i = blockIdx.x * 16 + warp;        // this warp's row
    float ax1 = sx1[i], ay1 = sy1[i], ax2 = sx2[i], ay2 = sy2[i], aa = sar[i];
    unsigned* dst = g_sup + ((size_t)b * KPRE + i) * 16;

    for (int wd = (i >> 5); wd < 16; wd++) {
        int j = (wd << 5) + lane;
        float ix1 = fmaxf(ax1, sx1[j]);
        float iy1 = fmaxf(ay1, sy1[j]);
        float ix2 = fminf(ax2, sx2[j]);
        float iy2 = fminf(ay2, sy2[j]);
        float iw = fmaxf(ix2 - ix1, 0.f);
        float ih = fmaxf(iy2 - iy1, 0.f);
        float inter = iw * ih;
        float uni = aa + sar[j] - inter;
        float iou = inter / (uni + 1e-9f);
        unsigned bits = __ballot_sync(FULLM, iou > IOU_TH);
        if (lane == 0) dst[wd] = bits;
    }
}

// ---------------------------------------------------------------------------
// K5: kept-box-centric greedy NMS (single warp, register-resident alive mask,
// early exit at 100 kept) + emit. One block (256 threads) per batch.
// ---------------------------------------------------------------------------
__global__ void k_nms(float* __restrict__ out, int out_size) {
    __shared__ unsigned ssup[KPRE * 16];   // 32 KB
    __shared__ unsigned svalid[16];
    __shared__ int skept[MAXOUT];
    __shared__ int snk;

    int b = blockIdx.x, tid = threadIdx.x;   // 256

    // stage suppression mask (L2-resident) into smem, vectorized
    {
        const uint4* src = (const uint4*)(g_sup + (size_t)b * KPRE * 16);
        uint4* dstv = (uint4*)ssup;
        for (int i = tid; i < KPRE * 16 / 4; i += 256) dstv[i] = src[i];
    }
    // build valid bitmask from bytes (uniform full-warp ballots)
#pragma unroll
    for (int r = 0; r < 2; r++) {
        int idx = r * 256 + tid;
        bool v = g_validb[b * KPRE + idx] != 0;
        unsigned w = __ballot_sync(FULLM, v);
        if ((tid & 31) == 0) svalid[idx >> 5] = w;
    }
    __syncthreads();

    if (tid < 32) {
        int lane = tid;
        unsigned alive = (lane < 16) ? svalid[lane] : 0u;
        int nk = 0;
        while (nk < MAXOUT) {
            unsigned bal = __ballot_sync(FULLM, alive != 0u);
            if (!bal) break;
            int tl = __ffs(bal) - 1;                       // first lane with alive bits
            unsigned w = __shfl_sync(FULLM, alive, tl);
            int bit = __ffs(w) - 1;
            int i = (tl << 5) + bit;                       // first alive index = next kept
            if (lane == 0) skept[nk] = i;
            nk++;
            unsigned sup = (lane < 16) ? ssup[i * 16 + lane] : 0u;
            alive &= ~sup;                                 // suppress overlapping later boxes
            if (lane == tl) alive &= ~(1u << bit);         // self
        }
        if (lane == 0) snk = nk;
    }
    __syncthreads();

    int nk = snk;
    float* dets = out + (size_t)b * MAXOUT * 7;
    bool has_mask = (out_size >= BATCH * MAXOUT * 7 + BATCH * MAXOUT);
    float* mask = out + (size_t)BATCH * MAXOUT * 7 + (size_t)b * MAXOUT;

    if (tid < MAXOUT) {
        int r = tid;
        if (r < nk) {
            int i = skept[r];
            const float* d = g_det + ((size_t)b * KPRE + i) * 7;
            float* o = dets + (size_t)r * 7;
#pragma unroll
            for (int c = 0; c < 7; c++) o[c] = d[c];
            if (has_mask) mask[r] = 1.0f;
        } else {
            float* o = dets + (size_t)r * 7;
#pragma unroll
            for (int c = 0; c < 7; c++) o[c] = 0.f;
            if (has_mask) mask[r] = 0.f;
        }
    }
}

// ---------------------------------------------------------------------------
extern "C" void kernel_launch(void* const* d_in, const int* in_sizes, int n_in,
                              void* d_out, int out_size) {
    (void)in_sizes; (void)n_in;
    const float* pred = (const float*)d_in[0];
    float* out = (float*)d_out;

    static_assert(NPRED % RPB == 0, "rows per block");
    static_assert((RPB * ROWF) % 4 == 0, "float4 staging");
    static_assert((NPRED * ROWF) % 4 == 0, "float4 batch base");
    static_assert((NCLS - 4) % 4 == 0, "4-way max chains cover classes");

    cudaFuncSetAttribute(k_select, cudaFuncAttributeMaxDynamicSharedMemorySize,
                         (NPRED + KPRE) * 8);

    dim3 gs(NPRED / RPB, BATCH);           // (70, 32)
    k_score<<<gs, 128>>>(pred);
    k_select<<<BATCH, 512, (NPRED + KPRE) * 8>>>();
    dim3 gg(KPRE / 8, BATCH);              // (64, 32)
    k_gather<<<gg, 256>>>(pred);
    dim3 gi(KPRE / 16, BATCH);             // (32, 32)
    k_iou<<<gi, 512>>>();
    k_nms<<<BATCH, 256>>>(out, out_size);
}